// round 1
// baseline (speedup 1.0000x reference)
#include <cuda_runtime.h>

#define NN 10000
#define EE 320000
#define FF 256

// ---------------- static scratch (no runtime allocation allowed) -------------
__device__ int   g_deg[NN];
__device__ int   g_row_ptr[NN + 1];
__device__ int   g_cursor[NN];
__device__ int   g_src_sorted[EE];
__device__ float g_val_sorted[EE];
__device__ float g_h[3 * NN * FF];   // x@W1 | x@W2 | x@W3
__device__ float g_t[NN * FF];       // spmm temp
__device__ float g_t2[NN * FF];      // spmm temp

// ---------------- CSR build --------------------------------------------------
__global__ void zero_deg_kernel() {
    int i = blockIdx.x * blockDim.x + threadIdx.x;
    if (i < NN) g_deg[i] = 0;
}

__global__ void hist_kernel(const int* __restrict__ dst) {
    int e = blockIdx.x * blockDim.x + threadIdx.x;
    if (e < EE) atomicAdd(&g_deg[dst[e]], 1);
}

// Single-block exclusive scan over NN degrees (1024 threads x 10 elems each).
__global__ void scan_kernel() {
    __shared__ int sums[1024];
    const int CH = (NN + 1023) / 1024;  // 10
    int t = threadIdx.x;
    int base = t * CH;
    int local[CH];
    int s = 0;
#pragma unroll
    for (int i = 0; i < CH; i++) {
        int idx = base + i;
        int v = (idx < NN) ? g_deg[idx] : 0;
        local[i] = s;
        s += v;
    }
    sums[t] = s;
    __syncthreads();
    // Hillis-Steele inclusive scan over 1024 partials
    for (int off = 1; off < 1024; off <<= 1) {
        int v = 0;
        if (t >= off) v = sums[t - off];
        __syncthreads();
        if (t >= off) sums[t] += v;
        __syncthreads();
    }
    int pre = (t > 0) ? sums[t - 1] : 0;
#pragma unroll
    for (int i = 0; i < CH; i++) {
        int idx = base + i;
        if (idx < NN) {
            int rp = pre + local[i];
            g_row_ptr[idx] = rp;
            g_cursor[idx] = rp;
        }
    }
    if (t == 1023) g_row_ptr[NN] = sums[1023];
}

__global__ void fill_kernel(const int* __restrict__ src,
                            const int* __restrict__ dst,
                            const float* __restrict__ vals) {
    int e = blockIdx.x * blockDim.x + threadIdx.x;
    if (e < EE) {
        int slot = atomicAdd(&g_cursor[dst[e]], 1);
        g_src_sorted[slot] = src[e];
        g_val_sorted[slot] = vals[e];
    }
}

// ---------------- GEMM: H[z] = X @ Wz  (fp32, 64x64 tile, 4x4 microtile) -----
__global__ __launch_bounds__(256) void gemm_kernel(
    const float* __restrict__ X,
    const float* __restrict__ W1,
    const float* __restrict__ W2,
    const float* __restrict__ W3) {
    const float* W = (blockIdx.z == 0) ? W1 : ((blockIdx.z == 1) ? W2 : W3);
    float* H = g_h + (size_t)blockIdx.z * NN * FF;

    __shared__ float As[16][64];  // [k][m] (transposed)
    __shared__ float Bs[16][64];  // [k][n]

    const int m0 = blockIdx.y * 64;
    const int n0 = blockIdx.x * 64;
    const int tid = threadIdx.x;
    const int tx = tid & 15;   // 0..15 -> n
    const int ty = tid >> 4;   // 0..15 -> m

    float acc[4][4];
#pragma unroll
    for (int i = 0; i < 4; i++)
#pragma unroll
        for (int j = 0; j < 4; j++) acc[i][j] = 0.0f;

    for (int k0 = 0; k0 < FF; k0 += 16) {
        // load A tile: 64 rows x 16 k, one float4 per thread, store transposed
        {
            int r = tid >> 2;       // 0..63
            int q = tid & 3;        // 0..3 -> which float4 of the 16 k's
            int row = m0 + r;
            float4 v = make_float4(0.f, 0.f, 0.f, 0.f);
            if (row < NN)
                v = *(const float4*)&X[(size_t)row * FF + k0 + q * 4];
            As[q * 4 + 0][r] = v.x;
            As[q * 4 + 1][r] = v.y;
            As[q * 4 + 2][r] = v.z;
            As[q * 4 + 3][r] = v.w;
        }
        // load B tile: 16 k x 64 n, one float4 per thread
        {
            int kr = tid >> 4;      // 0..15
            int qc = tid & 15;      // 0..15
            float4 v = *(const float4*)&W[(size_t)(k0 + kr) * FF + n0 + qc * 4];
            *(float4*)&Bs[kr][qc * 4] = v;
        }
        __syncthreads();

#pragma unroll
        for (int k = 0; k < 16; k++) {
            float4 a = *(const float4*)&As[k][ty * 4];
            float4 b = *(const float4*)&Bs[k][tx * 4];
            acc[0][0] += a.x * b.x; acc[0][1] += a.x * b.y;
            acc[0][2] += a.x * b.z; acc[0][3] += a.x * b.w;
            acc[1][0] += a.y * b.x; acc[1][1] += a.y * b.y;
            acc[1][2] += a.y * b.z; acc[1][3] += a.y * b.w;
            acc[2][0] += a.z * b.x; acc[2][1] += a.z * b.y;
            acc[2][2] += a.z * b.z; acc[2][3] += a.z * b.w;
            acc[3][0] += a.w * b.x; acc[3][1] += a.w * b.y;
            acc[3][2] += a.w * b.z; acc[3][3] += a.w * b.w;
        }
        __syncthreads();
    }

#pragma unroll
    for (int i = 0; i < 4; i++) {
        int row = m0 + ty * 4 + i;
        if (row < NN) {
            float4 v = make_float4(acc[i][0], acc[i][1], acc[i][2], acc[i][3]);
            *(float4*)&H[(size_t)row * FF + n0 + tx * 4] = v;
        }
    }
}

// ---------------- SpMM: out[row] (=|+=) sum_e val_e * h[src_e, :] ------------
// warp per destination row, 8 accumulators per lane (lane + 32*k covers 256)
__global__ __launch_bounds__(256) void spmm_kernel(
    const float* __restrict__ h, float* __restrict__ out, int accumulate) {
    int gtid = blockIdx.x * blockDim.x + threadIdx.x;
    int row = gtid >> 5;
    int lane = threadIdx.x & 31;
    if (row >= NN) return;

    int e = g_row_ptr[row];
    int end = g_row_ptr[row + 1];

    float acc[8];
#pragma unroll
    for (int k = 0; k < 8; k++) acc[k] = 0.0f;

    for (; e < end; e++) {
        int s = __ldg(&g_src_sorted[e]);
        float v = __ldg(&g_val_sorted[e]);
        const float* hr = h + (size_t)s * FF + lane;
#pragma unroll
        for (int k = 0; k < 8; k++)
            acc[k] += v * __ldg(hr + 32 * k);
    }

    float* orow = out + (size_t)row * FF + lane;
    if (accumulate) {
#pragma unroll
        for (int k = 0; k < 8; k++) orow[32 * k] += acc[k];
    } else {
#pragma unroll
        for (int k = 0; k < 8; k++) orow[32 * k] = acc[k];
    }
}

// ---------------- finalize: out = relu(out / 3) ------------------------------
__global__ void finalize_kernel(float* __restrict__ out, int n) {
    int i = blockIdx.x * blockDim.x + threadIdx.x;
    if (i < n) out[i] = fmaxf(out[i] * (1.0f / 3.0f), 0.0f);
}

// ---------------- launch -----------------------------------------------------
extern "C" void kernel_launch(void* const* d_in, const int* in_sizes, int n_in,
                              void* d_out, int out_size) {
    const float* x      = (const float*)d_in[0];
    const float* A_vals = (const float*)d_in[1];
    const float* W1     = (const float*)d_in[2];
    const float* W2     = (const float*)d_in[3];
    const float* W3     = (const float*)d_in[4];
    const int*   esrc   = (const int*)d_in[5];
    const int*   edst   = (const int*)d_in[6];
    float* out = (float*)d_out;

    void* p;
    cudaGetSymbolAddress(&p, g_h);  float* h  = (float*)p;
    cudaGetSymbolAddress(&p, g_t);  float* t  = (float*)p;
    cudaGetSymbolAddress(&p, g_t2); float* t2 = (float*)p;

    // CSR build (per launch; deterministic math, only bucket order varies)
    zero_deg_kernel<<<(NN + 255) / 256, 256>>>();
    hist_kernel<<<(EE + 255) / 256, 256>>>(edst);
    scan_kernel<<<1, 1024>>>();
    fill_kernel<<<(EE + 255) / 256, 256>>>(esrc, edst, A_vals);

    // H1|H2|H3 = x @ {W1,W2,W3}
    dim3 ggrid(FF / 64, (NN + 63) / 64, 3);
    gemm_kernel<<<ggrid, 256>>>(x, W1, W2, W3);

    const int sgrid = (NN * 32 + 255) / 256;
    // branch 1: out  = A @ H1
    spmm_kernel<<<sgrid, 256>>>(h, out, 0);
    // branch 2: out += A @ (A @ H2)
    spmm_kernel<<<sgrid, 256>>>(h + (size_t)NN * FF, t, 0);
    spmm_kernel<<<sgrid, 256>>>(t, out, 1);
    // branch 3: out += A @ (A @ (A @ H3))
    spmm_kernel<<<sgrid, 256>>>(h + 2 * (size_t)NN * FF, t, 0);
    spmm_kernel<<<sgrid, 256>>>(t, t2, 0);
    spmm_kernel<<<sgrid, 256>>>(t2, out, 1);

    // out = relu(out / 3)
    finalize_kernel<<<(NN * FF + 255) / 256, 256>>>(out, NN * FF);
}

// round 7
// speedup vs baseline: 2.0787x; 2.0787x over previous
#include <cuda_runtime.h>
#include <cstdint>

#define NN 10000
#define EE 320000
#define FF 256

// ---------------- static scratch (no runtime allocation allowed) -------------
__device__ int   g_deg[NN];
__device__ int   g_row_ptr[NN + 1];
__device__ int   g_cursor[NN];
__device__ int2  g_edge[EE];         // {src, __float_as_int(val)} bucketed by dst
__device__ float g_h[3 * NN * FF];   // b1 = x@W1 | b2 = x@W2 | b3 = x@W3

// ---------------- CSR build --------------------------------------------------
__global__ void hist_kernel(const int* __restrict__ dst) {
    int e4 = blockIdx.x * blockDim.x + threadIdx.x;
    if (e4 * 4 < EE) {
        int4 d = ((const int4*)dst)[e4];
        atomicAdd(&g_deg[d.x], 1);
        atomicAdd(&g_deg[d.y], 1);
        atomicAdd(&g_deg[d.z], 1);
        atomicAdd(&g_deg[d.w], 1);
    }
}

// Single-block exclusive scan over NN degrees (1024 threads x 10 elems each).
__global__ void scan_kernel() {
    __shared__ int sums[1024];
    const int CH = (NN + 1023) / 1024;  // 10
    int t = threadIdx.x;
    int base = t * CH;
    int local[CH];
    int s = 0;
#pragma unroll
    for (int i = 0; i < CH; i++) {
        int idx = base + i;
        int v = (idx < NN) ? g_deg[idx] : 0;
        local[i] = s;
        s += v;
    }
    sums[t] = s;
    __syncthreads();
    for (int off = 1; off < 1024; off <<= 1) {
        int v = 0;
        if (t >= off) v = sums[t - off];
        __syncthreads();
        if (t >= off) sums[t] += v;
        __syncthreads();
    }
    int pre = (t > 0) ? sums[t - 1] : 0;
#pragma unroll
    for (int i = 0; i < CH; i++) {
        int idx = base + i;
        if (idx < NN) {
            int rp = pre + local[i];
            g_row_ptr[idx] = rp;
            g_cursor[idx] = rp;
        }
    }
    if (t == 1023) g_row_ptr[NN] = sums[1023];
}

__global__ void fill_kernel(const int* __restrict__ src,
                            const int* __restrict__ dst,
                            const float* __restrict__ vals) {
    int e = blockIdx.x * blockDim.x + threadIdx.x;
    if (e < EE) {
        int slot = atomicAdd(&g_cursor[dst[e]], 1);
        g_edge[slot] = make_int2(src[e], __float_as_int(vals[e]));
    }
}

// ---------------- tf32 tensor-core GEMM: H[z] = X @ Wz -----------------------
// block tile 128x64, 8 warps (4x2) each 32x32, mma.m16n8k8.tf32
#define BM 128
#define BN 64
#define BK 16
#define ASTRIDE 20   // BK+4: conflict-free fragment reads
#define BSTRIDE 72   // BN+8: conflict-free fragment reads

__device__ __forceinline__ uint32_t f2tf32(float x) {
    uint32_t t;
    asm("cvt.rna.tf32.f32 %0, %1;" : "=r"(t) : "f"(x));
    return t;
}

__global__ __launch_bounds__(256) void gemm_tf32_kernel(
    const float* __restrict__ X,
    const float* __restrict__ W1,
    const float* __restrict__ W2,
    const float* __restrict__ W3) {
    const float* W = (blockIdx.z == 0) ? W1 : ((blockIdx.z == 1) ? W2 : W3);
    float* H = g_h + (size_t)blockIdx.z * NN * FF;

    __shared__ float As[BM * ASTRIDE];
    __shared__ float Bs[BK * BSTRIDE];

    const int tid  = threadIdx.x;
    const int warp = tid >> 5;
    const int lane = tid & 31;
    const int wm = warp >> 1;   // 0..3 -> m
    const int wn = warp & 1;    // 0..1 -> n
    const int m0 = blockIdx.y * BM;
    const int n0 = blockIdx.x * BN;
    const int grp = lane >> 2;  // 0..7
    const int tig = lane & 3;   // 0..3

    float acc[2][4][4];
#pragma unroll
    for (int i = 0; i < 2; i++)
#pragma unroll
        for (int j = 0; j < 4; j++)
#pragma unroll
            for (int q = 0; q < 4; q++) acc[i][j][q] = 0.0f;

    for (int k0 = 0; k0 < FF; k0 += BK) {
        // A tile: 128 rows x 16 k. 2 threads/row, 8 floats each.
        {
            int r  = tid >> 1;
            int c4 = (tid & 1) * 8;
            int row = m0 + r;
            float4 v0 = make_float4(0.f, 0.f, 0.f, 0.f);
            float4 v1 = make_float4(0.f, 0.f, 0.f, 0.f);
            if (row < NN) {
                v0 = *(const float4*)&X[(size_t)row * FF + k0 + c4];
                v1 = *(const float4*)&X[(size_t)row * FF + k0 + c4 + 4];
            }
            float* a = &As[r * ASTRIDE + c4];
            a[0] = v0.x; a[1] = v0.y; a[2] = v0.z; a[3] = v0.w;
            a[4] = v1.x; a[5] = v1.y; a[6] = v1.z; a[7] = v1.w;
        }
        // B tile: 16 k x 64 n. 1 float4 per thread.
        {
            int r = tid >> 4;
            int c = (tid & 15) * 4;
            float4 v = *(const float4*)&W[(size_t)(k0 + r) * FF + n0 + c];
            float* b = &Bs[r * BSTRIDE + c];
            b[0] = v.x; b[1] = v.y; b[2] = v.z; b[3] = v.w;
        }
        __syncthreads();

#pragma unroll
        for (int kk = 0; kk < BK; kk += 8) {
            uint32_t a[2][4];
            const int ar = wm * 32 + grp;
            const int ac = kk + tig;
#pragma unroll
            for (int mi = 0; mi < 2; mi++) {
                const float* ap = &As[(ar + mi * 16) * ASTRIDE];
                a[mi][0] = f2tf32(ap[ac]);
                a[mi][1] = f2tf32(ap[8 * ASTRIDE + ac]);
                a[mi][2] = f2tf32(ap[ac + 4]);
                a[mi][3] = f2tf32(ap[8 * ASTRIDE + ac + 4]);
            }
            uint32_t b[4][2];
            const int br = kk + tig;
            const int bc = wn * 32 + grp;
#pragma unroll
            for (int ni = 0; ni < 4; ni++) {
                b[ni][0] = f2tf32(Bs[br * BSTRIDE + bc + ni * 8]);
                b[ni][1] = f2tf32(Bs[(br + 4) * BSTRIDE + bc + ni * 8]);
            }
#pragma unroll
            for (int mi = 0; mi < 2; mi++)
#pragma unroll
                for (int ni = 0; ni < 4; ni++) {
                    asm volatile(
                        "mma.sync.aligned.m16n8k8.row.col.f32.tf32.tf32.f32 "
                        "{%0,%1,%2,%3},{%4,%5,%6,%7},{%8,%9},{%0,%1,%2,%3};"
                        : "+f"(acc[mi][ni][0]), "+f"(acc[mi][ni][1]),
                          "+f"(acc[mi][ni][2]), "+f"(acc[mi][ni][3])
                        : "r"(a[mi][0]), "r"(a[mi][1]), "r"(a[mi][2]), "r"(a[mi][3]),
                          "r"(b[ni][0]), "r"(b[ni][1]));
                }
        }
        __syncthreads();
    }

#pragma unroll
    for (int mi = 0; mi < 2; mi++)
#pragma unroll
        for (int ni = 0; ni < 4; ni++) {
            int row = m0 + wm * 32 + mi * 16 + grp;
            int col = n0 + wn * 32 + ni * 8 + tig * 2;
            if (row < NN) {
                float2 v = make_float2(acc[mi][ni][0], acc[mi][ni][1]);
                *(float2*)&H[(size_t)row * FF + col] = v;
            }
            if (row + 8 < NN) {
                float2 v = make_float2(acc[mi][ni][2], acc[mi][ni][3]);
                *(float2*)&H[(size_t)(row + 8) * FF + col] = v;
            }
        }
}

// ---------------- SpMM: 2 warps per dst row, one float4 per lane -------------
// warp w handles features [ (w&1)*128 , (w&1)*128+128 )
// mode 0: out = A@h   mode 1: out += A@h   mode 2: out = relu((A@h)/3)
__global__ __launch_bounds__(256) void spmm_kernel(
    const float* __restrict__ h, float* __restrict__ out, int mode) {
    int gw = (blockIdx.x * blockDim.x + threadIdx.x) >> 5;
    int row = gw >> 1;
    int half = gw & 1;
    int lane = threadIdx.x & 31;
    if (row >= NN) return;

    int e = g_row_ptr[row];
    int end = g_row_ptr[row + 1];

    const float* hb = h + half * 128 + lane * 4;
    float4 acc = make_float4(0.f, 0.f, 0.f, 0.f);

#pragma unroll 4
    for (; e < end; e++) {
        int2 ed = __ldg(&g_edge[e]);
        float v = __int_as_float(ed.y);
        float4 x = __ldg((const float4*)(hb + (size_t)ed.x * FF));
        acc.x += v * x.x; acc.y += v * x.y;
        acc.z += v * x.z; acc.w += v * x.w;
    }

    float4* o = (float4*)(out + (size_t)row * FF + half * 128) + lane;
    if (mode == 1) {
        float4 p = *o;
        p.x += acc.x; p.y += acc.y; p.z += acc.z; p.w += acc.w;
        *o = p;
    } else if (mode == 2) {
        const float inv3 = 1.0f / 3.0f;
        acc.x = fmaxf(acc.x * inv3, 0.f);
        acc.y = fmaxf(acc.y * inv3, 0.f);
        acc.z = fmaxf(acc.z * inv3, 0.f);
        acc.w = fmaxf(acc.w * inv3, 0.f);
        *o = acc;
    } else {
        *o = acc;
    }
}

// ---------------- launch -----------------------------------------------------
extern "C" void kernel_launch(void* const* d_in, const int* in_sizes, int n_in,
                              void* d_out, int out_size) {
    const float* x      = (const float*)d_in[0];
    const float* A_vals = (const float*)d_in[1];
    const float* W1     = (const float*)d_in[2];
    const float* W2     = (const float*)d_in[3];
    const float* W3     = (const float*)d_in[4];
    const int*   esrc   = (const int*)d_in[5];
    const int*   edst   = (const int*)d_in[6];
    float* out = (float*)d_out;

    void* p;
    cudaGetSymbolAddress(&p, g_h);
    float* b1 = (float*)p;
    float* b2 = b1 + (size_t)NN * FF;
    float* b3 = b2 + (size_t)NN * FF;

    void* pdeg;
    cudaGetSymbolAddress(&pdeg, g_deg);

    // CSR build
    cudaMemsetAsync(pdeg, 0, NN * sizeof(int));
    hist_kernel<<<(EE / 4 + 255) / 256, 256>>>(edst);
    scan_kernel<<<1, 1024>>>();
    fill_kernel<<<(EE + 255) / 256, 256>>>(esrc, edst, A_vals);

    // b1|b2|b3 = x @ {W1,W2,W3}  (tf32 tensor cores)
    dim3 ggrid(FF / BN, (NN + BM - 1) / BM, 3);
    gemm_tf32_kernel<<<ggrid, 256>>>(x, W1, W2, W3);

    // Horner: out = relu( A(b1 + A(b2 + A b3)) / 3 )
    const int sgrid = (NN * 2 * 32 + 255) / 256;
    spmm_kernel<<<sgrid, 256>>>(b3, b2, 1);   // b2 += A @ b3
    spmm_kernel<<<sgrid, 256>>>(b2, b1, 1);   // b1 += A @ b2
    spmm_kernel<<<sgrid, 256>>>(b1, out, 2);  // out = relu((A @ b1)/3)
}

// round 8
// speedup vs baseline: 2.0902x; 1.0055x over previous
#include <cuda_runtime.h>
#include <cstdint>

#define NN 10000
#define EE 320000
#define FF 256

// ---------------- static scratch (no runtime allocation allowed) -------------
__device__ int   g_deg[NN];
__device__ int   g_row_ptr[NN + 1];
__device__ int   g_cursor[NN];
__device__ int2  g_edge[EE];         // {src, __float_as_int(val)} bucketed by dst
__device__ float g_h[3 * NN * FF];   // b1 = x@W1 | b2 = x@W2 | b3 = x@W3

// ---------------- CSR build --------------------------------------------------
__global__ void hist_kernel(const int* __restrict__ dst) {
    int e4 = blockIdx.x * blockDim.x + threadIdx.x;
    if (e4 * 4 < EE) {
        int4 d = ((const int4*)dst)[e4];
        atomicAdd(&g_deg[d.x], 1);
        atomicAdd(&g_deg[d.y], 1);
        atomicAdd(&g_deg[d.z], 1);
        atomicAdd(&g_deg[d.w], 1);
    }
}

// Single-block exclusive scan over NN degrees (1024 threads x 10 elems each).
__global__ void scan_kernel() {
    __shared__ int sums[1024];
    const int CH = (NN + 1023) / 1024;  // 10
    int t = threadIdx.x;
    int base = t * CH;
    int local[CH];
    int s = 0;
#pragma unroll
    for (int i = 0; i < CH; i++) {
        int idx = base + i;
        int v = (idx < NN) ? g_deg[idx] : 0;
        local[i] = s;
        s += v;
    }
    sums[t] = s;
    __syncthreads();
    for (int off = 1; off < 1024; off <<= 1) {
        int v = 0;
        if (t >= off) v = sums[t - off];
        __syncthreads();
        if (t >= off) sums[t] += v;
        __syncthreads();
    }
    int pre = (t > 0) ? sums[t - 1] : 0;
#pragma unroll
    for (int i = 0; i < CH; i++) {
        int idx = base + i;
        if (idx < NN) {
            int rp = pre + local[i];
            g_row_ptr[idx] = rp;
            g_cursor[idx] = rp;
        }
    }
    if (t == 1023) g_row_ptr[NN] = sums[1023];
}

__global__ void fill_kernel(const int* __restrict__ src,
                            const int* __restrict__ dst,
                            const float* __restrict__ vals) {
    int e = blockIdx.x * blockDim.x + threadIdx.x;
    if (e < EE) {
        int slot = atomicAdd(&g_cursor[dst[e]], 1);
        g_edge[slot] = make_int2(src[e], __float_as_int(vals[e]));
    }
}

// ---------------- tf32 tensor-core GEMM: H[z] = X @ Wz -----------------------
// 128x64 block tile, 8 warps (4x2) each 32x32, mma.m16n8k8.tf32.
// A stored pair-permuted (k, k+4 adjacent) so fragment loads are LDS.64;
// tiles pre-converted to tf32 at store; double-buffered smem, 1 sync/iter.
#define BM 128
#define BN 64
#define BK 16
#define ASTRIDE 24   // even (v2 align) + conflict-free per 16-lane phase
#define BSTRIDE 72

__device__ __forceinline__ uint32_t f2tf32(float x) {
    uint32_t t;
    asm("cvt.rna.tf32.f32 %0, %1;" : "=r"(t) : "f"(x));
    return t;
}
__device__ __forceinline__ float tf32f(float x) {
    return __uint_as_float(f2tf32(x));
}

__global__ __launch_bounds__(256) void gemm_tf32_kernel(
    const float* __restrict__ X,
    const float* __restrict__ W1,
    const float* __restrict__ W2,
    const float* __restrict__ W3) {
    const float* W = (blockIdx.z == 0) ? W1 : ((blockIdx.z == 1) ? W2 : W3);
    float* H = g_h + (size_t)blockIdx.z * NN * FF;

    __shared__ float As[2][BM * ASTRIDE];
    __shared__ float Bs[2][BK * BSTRIDE];

    const int tid  = threadIdx.x;
    const int warp = tid >> 5;
    const int lane = tid & 31;
    const int wm = warp >> 1;   // 0..3 -> m
    const int wn = warp & 1;    // 0..1 -> n
    const int m0 = blockIdx.y * BM;
    const int n0 = blockIdx.x * BN;
    const int grp = lane >> 2;  // 0..7
    const int tig = lane & 3;   // 0..3

    // loader coordinates
    const int lar = tid >> 1;          // A row 0..127
    const int lac = (tid & 1) * 8;     // A k-base (0 or 8)
    const int lbk = tid >> 4;          // B k 0..15
    const int lbn = (tid & 15) * 4;    // B n

    float acc[2][4][4];
#pragma unroll
    for (int i = 0; i < 2; i++)
#pragma unroll
        for (int j = 0; j < 4; j++)
#pragma unroll
            for (int q = 0; q < 4; q++) acc[i][j][q] = 0.0f;

    float4 av0, av1, bv;

    // prefetch tile k0=0
    {
        int row = m0 + lar;
        av0 = make_float4(0.f, 0.f, 0.f, 0.f);
        av1 = make_float4(0.f, 0.f, 0.f, 0.f);
        if (row < NN) {
            av0 = *(const float4*)&X[(size_t)row * FF + lac];
            av1 = *(const float4*)&X[(size_t)row * FF + lac + 4];
        }
        bv = *(const float4*)&W[(size_t)lbk * FF + n0 + lbn];
    }
    // store tile 0 (cvt to tf32, pair-permuted A: (k,k+4) adjacent)
    {
        float2* a = (float2*)&As[0][lar * ASTRIDE + lac];
        a[0] = make_float2(tf32f(av0.x), tf32f(av1.x));
        a[1] = make_float2(tf32f(av0.y), tf32f(av1.y));
        a[2] = make_float2(tf32f(av0.z), tf32f(av1.z));
        a[3] = make_float2(tf32f(av0.w), tf32f(av1.w));
        float* b = &Bs[0][lbk * BSTRIDE + lbn];
        b[0] = tf32f(bv.x); b[1] = tf32f(bv.y);
        b[2] = tf32f(bv.z); b[3] = tf32f(bv.w);
    }
    __syncthreads();

    for (int k0 = 0; k0 < FF; k0 += BK) {
        const int buf = (k0 / BK) & 1;
        const int nxt = k0 + BK;
        if (nxt < FF) {
            int row = m0 + lar;
            av0 = make_float4(0.f, 0.f, 0.f, 0.f);
            av1 = make_float4(0.f, 0.f, 0.f, 0.f);
            if (row < NN) {
                av0 = *(const float4*)&X[(size_t)row * FF + nxt + lac];
                av1 = *(const float4*)&X[(size_t)row * FF + nxt + lac + 4];
            }
            bv = *(const float4*)&W[(size_t)(nxt + lbk) * FF + n0 + lbn];
        }

#pragma unroll
        for (int kk = 0; kk < BK; kk += 8) {
            uint32_t a[2][4];
            const int ar = wm * 32 + grp;
#pragma unroll
            for (int mi = 0; mi < 2; mi++) {
                float2 p0 = *(const float2*)&As[buf][(ar + mi * 16) * ASTRIDE + kk + tig * 2];
                float2 p1 = *(const float2*)&As[buf][(ar + mi * 16 + 8) * ASTRIDE + kk + tig * 2];
                a[mi][0] = __float_as_uint(p0.x);
                a[mi][1] = __float_as_uint(p1.x);
                a[mi][2] = __float_as_uint(p0.y);
                a[mi][3] = __float_as_uint(p1.y);
            }
            uint32_t b[4][2];
            const int br = kk + tig;
            const int bc = wn * 32 + grp;
#pragma unroll
            for (int ni = 0; ni < 4; ni++) {
                b[ni][0] = __float_as_uint(Bs[buf][br * BSTRIDE + bc + ni * 8]);
                b[ni][1] = __float_as_uint(Bs[buf][(br + 4) * BSTRIDE + bc + ni * 8]);
            }
#pragma unroll
            for (int mi = 0; mi < 2; mi++)
#pragma unroll
                for (int ni = 0; ni < 4; ni++) {
                    asm volatile(
                        "mma.sync.aligned.m16n8k8.row.col.f32.tf32.tf32.f32 "
                        "{%0,%1,%2,%3},{%4,%5,%6,%7},{%8,%9},{%0,%1,%2,%3};"
                        : "+f"(acc[mi][ni][0]), "+f"(acc[mi][ni][1]),
                          "+f"(acc[mi][ni][2]), "+f"(acc[mi][ni][3])
                        : "r"(a[mi][0]), "r"(a[mi][1]), "r"(a[mi][2]), "r"(a[mi][3]),
                          "r"(b[ni][0]), "r"(b[ni][1]));
                }
        }

        if (nxt < FF) {
            const int nb = buf ^ 1;
            float2* a = (float2*)&As[nb][lar * ASTRIDE + lac];
            a[0] = make_float2(tf32f(av0.x), tf32f(av1.x));
            a[1] = make_float2(tf32f(av0.y), tf32f(av1.y));
            a[2] = make_float2(tf32f(av0.z), tf32f(av1.z));
            a[3] = make_float2(tf32f(av0.w), tf32f(av1.w));
            float* b = &Bs[nb][lbk * BSTRIDE + lbn];
            b[0] = tf32f(bv.x); b[1] = tf32f(bv.y);
            b[2] = tf32f(bv.z); b[3] = tf32f(bv.w);
        }
        __syncthreads();
    }

#pragma unroll
    for (int mi = 0; mi < 2; mi++)
#pragma unroll
        for (int ni = 0; ni < 4; ni++) {
            int row = m0 + wm * 32 + mi * 16 + grp;
            int col = n0 + wn * 32 + ni * 8 + tig * 2;
            if (row < NN) {
                float2 v = make_float2(acc[mi][ni][0], acc[mi][ni][1]);
                *(float2*)&H[(size_t)row * FF + col] = v;
            }
            if (row + 8 < NN) {
                float2 v = make_float2(acc[mi][ni][2], acc[mi][ni][3]);
                *(float2*)&H[(size_t)(row + 8) * FF + col] = v;
            }
        }
}

// ---------------- SpMM: 2 warps per dst row, one float4 per lane -------------
// warp w handles features [ (w&1)*128 , (w&1)*128+128 )
// mode 0: out = A@h   mode 1: out += A@h   mode 2: out = relu((A@h)/3)
__global__ __launch_bounds__(256) void spmm_kernel(
    const float* __restrict__ h, float* __restrict__ out, int mode) {
    int gw = (blockIdx.x * blockDim.x + threadIdx.x) >> 5;
    int row = gw >> 1;
    int half = gw & 1;
    int lane = threadIdx.x & 31;
    if (row >= NN) return;

    int e = g_row_ptr[row];
    int end = g_row_ptr[row + 1];

    const float* hb = h + half * 128 + lane * 4;
    float4 acc = make_float4(0.f, 0.f, 0.f, 0.f);

#pragma unroll 4
    for (; e < end; e++) {
        int2 ed = __ldg(&g_edge[e]);
        float v = __int_as_float(ed.y);
        float4 x = __ldg((const float4*)(hb + (size_t)ed.x * FF));
        acc.x += v * x.x; acc.y += v * x.y;
        acc.z += v * x.z; acc.w += v * x.w;
    }

    float4* o = (float4*)(out + (size_t)row * FF + half * 128) + lane;
    if (mode == 1) {
        float4 p = *o;
        p.x += acc.x; p.y += acc.y; p.z += acc.z; p.w += acc.w;
        *o = p;
    } else if (mode == 2) {
        const float inv3 = 1.0f / 3.0f;
        acc.x = fmaxf(acc.x * inv3, 0.f);
        acc.y = fmaxf(acc.y * inv3, 0.f);
        acc.z = fmaxf(acc.z * inv3, 0.f);
        acc.w = fmaxf(acc.w * inv3, 0.f);
        *o = acc;
    } else {
        *o = acc;
    }
}

// ---------------- launch -----------------------------------------------------
extern "C" void kernel_launch(void* const* d_in, const int* in_sizes, int n_in,
                              void* d_out, int out_size) {
    const float* x      = (const float*)d_in[0];
    const float* A_vals = (const float*)d_in[1];
    const float* W1     = (const float*)d_in[2];
    const float* W2     = (const float*)d_in[3];
    const float* W3     = (const float*)d_in[4];
    const int*   esrc   = (const int*)d_in[5];
    const int*   edst   = (const int*)d_in[6];
    float* out = (float*)d_out;

    void* p;
    cudaGetSymbolAddress(&p, g_h);
    float* b1 = (float*)p;
    float* b2 = b1 + (size_t)NN * FF;
    float* b3 = b2 + (size_t)NN * FF;

    void* pdeg;
    cudaGetSymbolAddress(&pdeg, g_deg);

    // CSR build
    cudaMemsetAsync(pdeg, 0, NN * sizeof(int));
    hist_kernel<<<(EE / 4 + 255) / 256, 256>>>(edst);
    scan_kernel<<<1, 1024>>>();
    fill_kernel<<<(EE + 255) / 256, 256>>>(esrc, edst, A_vals);

    // b1|b2|b3 = x @ {W1,W2,W3}  (tf32 tensor cores)
    dim3 ggrid(FF / BN, (NN + BM - 1) / BM, 3);
    gemm_tf32_kernel<<<ggrid, 256>>>(x, W1, W2, W3);

    // Horner: out = relu( A(b1 + A(b2 + A b3)) / 3 )
    const int sgrid = (NN * 2 * 32 + 255) / 256;
    spmm_kernel<<<sgrid, 256>>>(b3, b2, 1);   // b2 += A @ b3
    spmm_kernel<<<sgrid, 256>>>(b2, b1, 1);   // b1 += A @ b2
    spmm_kernel<<<sgrid, 256>>>(b1, out, 2);  // out = relu((A @ b1)/3)
}